// round 8
// baseline (speedup 1.0000x reference)
#include <cuda_runtime.h>
#include <cuda_fp16.h>
#include <cstdint>

#define DINL __device__ __forceinline__

namespace {
constexpr int KDIM = 4096;   // in_features
constexpr int NOUT = 4096;   // out_features
constexpr int MTOK = 1024;   // tokens

constexpr int BM = 64;       // CTA tile M
constexpr int BN = 128;      // CTA tile N
constexpr int BK = 64;       // K per stage (chunk)
constexpr int NUM_K = KDIM / BK;   // 64
constexpr int THREADS = 128; // 4 warps: 2 in M x 2 in N (32x64 per warp)

constexpr int A_ROW_B = 144;                // 64 halves (128B) + 16B pad -> conflict-free ldmatrix
constexpr int B_ROW_B = 144;
constexpr int A_BYTES = BM * A_ROW_B;       // 9216
constexpr int B_BYTES = BN * B_ROW_B;       // 18432
constexpr int STAGE_BYTES = A_BYTES + B_BYTES;   // 27648
constexpr int SMEM_TOTAL = 2 * STAGE_BYTES;      // 55296 -> 3 CTAs/SM (166KB)

constexpr int CONV_BLOCKS = (MTOK * KDIM / 16) / 256;           // 1024  (4 float4/thread)
constexpr int PACK_BLOCKS = (NOUT * (KDIM / 256)) / 8;          // 8192  (1 warp = 256 K-values)
}  // namespace

// Scratch (static device globals: allowed; no runtime allocation).
__device__ __align__(16) __half   g_xh[(size_t)MTOK * KDIM];          // 8 MB fp16 x
__device__ __align__(16) unsigned g_wbits[(KDIM / 32) * NOUT];        // 2 MB packed binarized W, [kword][n]

DINL uint32_t smem_u32(const void* p) {
    uint32_t a;
    asm("{ .reg .u64 t; cvta.to.shared.u64 t, %1; cvt.u32.u64 %0, t; }" : "=r"(a) : "l"(p));
    return a;
}

// ---------------- fused prepass: x->fp16  +  binarize/bit-pack W ----------------
__global__ void __launch_bounds__(256) prepass_kernel(const float* __restrict__ x,
                                                      const float* __restrict__ w) {
    if (blockIdx.x < CONV_BLOCKS) {
        // 4 independent float4 per thread (MLP=4)
        int base = blockIdx.x * 256 + threadIdx.x;
        float4 v[4];
        #pragma unroll
        for (int j = 0; j < 4; ++j)
            v[j] = __ldcs((const float4*)x + base + j * (CONV_BLOCKS * 256));
        #pragma unroll
        for (int j = 0; j < 4; ++j) {
            __half2 h0 = __floats2half2_rn(v[j].x, v[j].y);
            __half2 h1 = __floats2half2_rn(v[j].z, v[j].w);
            uint2 u;
            u.x = *(const uint32_t*)&h0;
            u.y = *(const uint32_t*)&h1;
            *(uint2*)(&g_xh[(size_t)(base + j * (CONV_BLOCKS * 256)) * 4]) = u;
        }
    } else {
        // one warp packs 256 K-values (2x float4/lane) of one W row into 8 bit-words
        int pb = blockIdx.x - CONV_BLOCKS;
        int lane = threadIdx.x & 31;
        int wg = pb * 8 + (threadIdx.x >> 5);   // global warp id
        int n = wg & (NOUT - 1);
        int kb = wg >> 12;                      // 256-wide K block, 0..15
        const float4* src = (const float4*)(w + (size_t)n * KDIM + kb * 256);
        const float4 v0 = __ldcs(src + lane);
        const float4 v1 = __ldcs(src + 32 + lane);
        #pragma unroll
        for (int half = 0; half < 2; ++half) {
            const float4& v = half ? v1 : v0;
            unsigned nib = (v.x > 0.f ? 1u : 0u) | (v.y > 0.f ? 2u : 0u)
                         | (v.z > 0.f ? 4u : 0u) | (v.w > 0.f ? 8u : 0u);
            unsigned a = nib | (__shfl_down_sync(0xFFFFFFFFu, nib, 1) << 4);
            unsigned b = a   | (__shfl_down_sync(0xFFFFFFFFu, a, 2)   << 8);
            unsigned m = b   | (__shfl_down_sync(0xFFFFFFFFu, b, 4)   << 16);
            if ((lane & 7) == 0) {
                int c = kb * 8 + half * 4 + (lane >> 3);
                g_wbits[c * NOUT + n] = m;
            }
        }
    }
}

// ---------------- main GEMM: out = (x_fp16 @ Wb^T) * round(max(s,1)) ----------------
// f16-accumulate HMMA; fp32 promotion every chunk (64 K) via k8 identity-B MMA.
// Small CTAs (128 thr, 55KB smem, <=170 regs) -> 3 independent CTAs/SM.
__global__ void __launch_bounds__(THREADS, 3)
SBNLinear_39754217292616_kernel(const float* __restrict__ s, float* __restrict__ out) {
    extern __shared__ char smem[];
    const uint32_t sb = smem_u32(smem);
    const int tid = threadIdx.x;
    const int lane = tid & 31;
    const int wid = tid >> 5;                // 0..3
    const int m0 = blockIdx.x * BM;
    const int n0 = blockIdx.y * BN;
    const int m_off = (wid >> 1) * 32;       // 2 warps in M, 32 rows each
    const int n_off = (wid & 1) * 64;        // 2 warps in N, 64 cols each

    // identity fragment (fp16 I8) for the k8 promotion MMA
    const int q = lane >> 2, p = lane & 3;
    const uint32_t idf = ((2 * p == q) ? 0x3C00u : 0u) | ((2 * p + 1 == q) ? 0x3C000000u : 0u);

    float acc32[2][8][4];
    uint32_t acc16[2][8][2];
    #pragma unroll
    for (int mi = 0; mi < 2; ++mi)
        #pragma unroll
        for (int nj = 0; nj < 8; ++nj) {
            acc16[mi][nj][0] = 0u; acc16[mi][nj][1] = 0u;
            #pragma unroll
            for (int e = 0; e < 4; ++e) acc32[mi][nj][e] = 0.0f;
        }

    // A tile: 64 rows x 128B = 512 x 16B, 4 cp.async per thread
    auto issueA = [&](int c, int buf) {
        #pragma unroll
        for (int i = 0; i < 4; ++i) {
            int qx = tid + i * THREADS;          // 0..511
            int row = qx >> 3;
            int ch = qx & 7;
            uint32_t dst = sb + buf * STAGE_BYTES + row * A_ROW_B + ch * 16;
            const __half* src = &g_xh[(size_t)(m0 + row) * KDIM + c * BK + ch * 8];
            asm volatile("cp.async.cg.shared.global [%0], [%1], 16;\n" :: "r"(dst), "l"(src) : "memory");
        }
    };
    // one thread per B row: expand 64 bits -> 64 fp16 {0,1} (128B)
    auto stsB = [&](uint2 bits, int buf) {
        uint32_t dst = sb + buf * STAGE_BYTES + A_BYTES + tid * B_ROW_B;
        #pragma unroll
        for (int j = 0; j < 8; ++j) {
            unsigned b8 = ((j < 4 ? bits.x : bits.y) >> ((j & 3) * 8)) & 0xFFu;
            uint32_t u0, u1, u2, u3;
            u0 = (b8 & 1u   ? 0x3C00u : 0u) | (b8 & 2u   ? 0x3C000000u : 0u);
            u1 = (b8 & 4u   ? 0x3C00u : 0u) | (b8 & 8u   ? 0x3C000000u : 0u);
            u2 = (b8 & 16u  ? 0x3C00u : 0u) | (b8 & 32u  ? 0x3C000000u : 0u);
            u3 = (b8 & 64u  ? 0x3C00u : 0u) | (b8 & 128u ? 0x3C000000u : 0u);
            asm volatile("st.shared.v4.b32 [%0], {%1,%2,%3,%4};\n"
                         :: "r"(dst + j * 16), "r"(u0), "r"(u1), "r"(u2), "r"(u3) : "memory");
        }
    };
    auto loadBits = [&](int c) -> uint2 {
        uint2 r;
        r.x = g_wbits[(2 * c) * NOUT + n0 + tid];
        r.y = g_wbits[(2 * c + 1) * NOUT + n0 + tid];
        return r;
    };

    // prologue: fill buffer 0 with chunk 0
    issueA(0, 0);
    asm volatile("cp.async.commit_group;\n" ::: "memory");
    stsB(loadBits(0), 0);
    uint2 bits_next = loadBits(1);

    for (int c = 0; c < NUM_K; ++c) {
        const int cur = c & 1;
        asm volatile("cp.async.wait_group 0;\n" ::: "memory");   // A(c) resident
        __syncthreads();                                         // stsB(c) visible, buf (c+1)&1 free

        const int cn = c + 1;
        if (cn < NUM_K) {
            const int nxt = cn & 1;
            stsB(bits_next, nxt);
            issueA(cn, nxt);
            asm volatile("cp.async.commit_group;\n" ::: "memory");
            if (cn + 1 < NUM_K)
                bits_next = loadBits(cn + 1);
        }

        const uint32_t ab = sb + cur * STAGE_BYTES;
        const uint32_t bb = ab + A_BYTES;
        #pragma unroll
        for (int h = 0; h < 4; ++h) {
            uint32_t a[2][4];
            #pragma unroll
            for (int mi = 0; mi < 2; ++mi) {
                uint32_t addr = ab + (uint32_t)(m_off + 16 * mi + (lane & 15)) * A_ROW_B
                                   + (uint32_t)(2 * h + (lane >> 4)) * 16;
                asm volatile("ldmatrix.sync.aligned.m8n8.x4.shared.b16 {%0,%1,%2,%3}, [%4];\n"
                             : "=r"(a[mi][0]), "=r"(a[mi][1]), "=r"(a[mi][2]), "=r"(a[mi][3])
                             : "r"(addr));
            }
            #pragma unroll
            for (int g = 0; g < 4; ++g) {
                int row = n_off + 16 * g + ((lane >> 4) << 3) + (lane & 7);
                uint32_t addr = bb + (uint32_t)row * B_ROW_B
                                   + (uint32_t)(2 * h + ((lane >> 3) & 1)) * 16;
                uint32_t r0, r1, r2, r3;
                asm volatile("ldmatrix.sync.aligned.m8n8.x4.shared.b16 {%0,%1,%2,%3}, [%4];\n"
                             : "=r"(r0), "=r"(r1), "=r"(r2), "=r"(r3) : "r"(addr));
                #pragma unroll
                for (int mi = 0; mi < 2; ++mi) {
                    asm volatile(
                        "mma.sync.aligned.m16n8k16.row.col.f16.f16.f16.f16 "
                        "{%0,%1}, {%2,%3,%4,%5}, {%6,%7}, {%0,%1};\n"
                        : "+r"(acc16[mi][2 * g][0]), "+r"(acc16[mi][2 * g][1])
                        : "r"(a[mi][0]), "r"(a[mi][1]), "r"(a[mi][2]), "r"(a[mi][3]),
                          "r"(r0), "r"(r1));
                    asm volatile(
                        "mma.sync.aligned.m16n8k16.row.col.f16.f16.f16.f16 "
                        "{%0,%1}, {%2,%3,%4,%5}, {%6,%7}, {%0,%1};\n"
                        : "+r"(acc16[mi][2 * g + 1][0]), "+r"(acc16[mi][2 * g + 1][1])
                        : "r"(a[mi][0]), "r"(a[mi][1]), "r"(a[mi][2]), "r"(a[mi][3]),
                          "r"(r2), "r"(r3));
                }
            }
        }

        // promote f16 segment accumulators (64 K-steps) into fp32 on the tensor pipe:
        // D-fragment {c01,c23} IS the k8 A-fragment -> acc32 += acc16 x I8
        #pragma unroll
        for (int mi = 0; mi < 2; ++mi)
            #pragma unroll
            for (int nj = 0; nj < 8; ++nj) {
                asm volatile(
                    "mma.sync.aligned.m16n8k8.row.col.f32.f16.f16.f32 "
                    "{%0,%1,%2,%3}, {%4,%5}, {%6}, {%0,%1,%2,%3};\n"
                    : "+f"(acc32[mi][nj][0]), "+f"(acc32[mi][nj][1]),
                      "+f"(acc32[mi][nj][2]), "+f"(acc32[mi][nj][3])
                    : "r"(acc16[mi][nj][0]), "r"(acc16[mi][nj][1]), "r"(idf));
                acc16[mi][nj][0] = 0u;
                acc16[mi][nj][1] = 0u;
            }
    }

    // epilogue: fuse s_eff = rint(max(s,1)) and store
    float sc[8][2];
    #pragma unroll
    for (int nj = 0; nj < 8; ++nj) {
        int col = n0 + n_off + 8 * nj + 2 * (lane & 3);
        sc[nj][0] = rintf(fmaxf(s[col], 1.0f));
        sc[nj][1] = rintf(fmaxf(s[col + 1], 1.0f));
    }
    #pragma unroll
    for (int mi = 0; mi < 2; ++mi) {
        int r0 = m0 + m_off + 16 * mi + (lane >> 2);
        #pragma unroll
        for (int nj = 0; nj < 8; ++nj) {
            int col = n0 + n_off + 8 * nj + 2 * (lane & 3);
            float2 v0 = make_float2(acc32[mi][nj][0] * sc[nj][0], acc32[mi][nj][1] * sc[nj][1]);
            float2 v1 = make_float2(acc32[mi][nj][2] * sc[nj][0], acc32[mi][nj][3] * sc[nj][1]);
            *(float2*)(out + (size_t)r0 * NOUT + col) = v0;
            *(float2*)(out + (size_t)(r0 + 8) * NOUT + col) = v1;
        }
    }
}

extern "C" void kernel_launch(void* const* d_in, const int* in_sizes, int n_in,
                              void* d_out, int out_size) {
    (void)in_sizes; (void)n_in; (void)out_size;
    const float* x = (const float*)d_in[0];
    const float* w = (const float*)d_in[1];
    const float* s = (const float*)d_in[2];
    float* out = (float*)d_out;

    prepass_kernel<<<CONV_BLOCKS + PACK_BLOCKS, 256>>>(x, w);

    cudaFuncSetAttribute(SBNLinear_39754217292616_kernel,
                         cudaFuncAttributeMaxDynamicSharedMemorySize, SMEM_TOTAL);
    dim3 grid(MTOK / BM, NOUT / BN);   // 16 x 32 = 512 CTAs, 3 resident/SM
    SBNLinear_39754217292616_kernel<<<grid, THREADS, SMEM_TOTAL>>>(s, out);
}

// round 9
// speedup vs baseline: 1.0202x; 1.0202x over previous
#include <cuda_runtime.h>
#include <cuda_fp16.h>
#include <cstdint>

#define DINL __device__ __forceinline__

namespace {
constexpr int KDIM = 4096;   // in_features
constexpr int NOUT = 4096;   // out_features
constexpr int MTOK = 1024;   // tokens

constexpr int BM = 64;       // CTA tile M
constexpr int BN = 128;      // CTA tile N
constexpr int BK = 64;       // K per stage (chunk)
constexpr int NUM_K = KDIM / BK;   // 64
constexpr int THREADS = 128; // 4 warps: 2 in M x 2 in N (32x64 per warp)

constexpr int A_ROW_B = 144;                // 64 halves (128B) + 16B pad -> conflict-free ldmatrix
constexpr int B_ROW_B = 144;
constexpr int A_BYTES = BM * A_ROW_B;       // 9216
constexpr int B_BYTES = BN * B_ROW_B;       // 18432
constexpr int STAGE_BYTES = A_BYTES + B_BYTES;   // 27648
constexpr int SMEM_TOTAL = 2 * STAGE_BYTES;      // 55296 -> 3 CTAs/SM (166KB)

constexpr int CONV_BLOCKS = (MTOK * KDIM / 16) / 256;           // 1024  (4 float4/thread)
constexpr int PACK_BLOCKS = (NOUT * (KDIM / 256)) / 8;          // 8192  (1 warp = 256 K-values)
}  // namespace

// Scratch (static device globals: allowed; no runtime allocation).
__device__ __align__(16) __half   g_xh[(size_t)MTOK * KDIM];          // 8 MB fp16 x
__device__ __align__(16) unsigned g_wbits[(KDIM / 32) * NOUT];        // 2 MB packed binarized W, [kword][n]

DINL uint32_t smem_u32(const void* p) {
    uint32_t a;
    asm("{ .reg .u64 t; cvta.to.shared.u64 t, %1; cvt.u32.u64 %0, t; }" : "=r"(a) : "l"(p));
    return a;
}

// ---------------- fused prepass: x->fp16  +  binarize/bit-pack W ----------------
__global__ void __launch_bounds__(256) prepass_kernel(const float* __restrict__ x,
                                                      const float* __restrict__ w) {
    if (blockIdx.x < CONV_BLOCKS) {
        // 4 independent float4 per thread (MLP=4)
        int base = blockIdx.x * 256 + threadIdx.x;
        float4 v[4];
        #pragma unroll
        for (int j = 0; j < 4; ++j)
            v[j] = __ldcs((const float4*)x + base + j * (CONV_BLOCKS * 256));
        #pragma unroll
        for (int j = 0; j < 4; ++j) {
            __half2 h0 = __floats2half2_rn(v[j].x, v[j].y);
            __half2 h1 = __floats2half2_rn(v[j].z, v[j].w);
            uint2 u;
            u.x = *(const uint32_t*)&h0;
            u.y = *(const uint32_t*)&h1;
            *(uint2*)(&g_xh[(size_t)(base + j * (CONV_BLOCKS * 256)) * 4]) = u;
        }
    } else {
        // one warp packs 256 K-values (2x float4/lane) of one W row into 8 bit-words
        int pb = blockIdx.x - CONV_BLOCKS;
        int lane = threadIdx.x & 31;
        int wg = pb * 8 + (threadIdx.x >> 5);   // global warp id
        int n = wg & (NOUT - 1);
        int kb = wg >> 12;                      // 256-wide K block, 0..15
        const float4* src = (const float4*)(w + (size_t)n * KDIM + kb * 256);
        const float4 v0 = __ldcs(src + lane);
        const float4 v1 = __ldcs(src + 32 + lane);
        #pragma unroll
        for (int half = 0; half < 2; ++half) {
            const float4& v = half ? v1 : v0;
            unsigned nib = (v.x > 0.f ? 1u : 0u) | (v.y > 0.f ? 2u : 0u)
                         | (v.z > 0.f ? 4u : 0u) | (v.w > 0.f ? 8u : 0u);
            unsigned a = nib | (__shfl_down_sync(0xFFFFFFFFu, nib, 1) << 4);
            unsigned b = a   | (__shfl_down_sync(0xFFFFFFFFu, a, 2)   << 8);
            unsigned m = b   | (__shfl_down_sync(0xFFFFFFFFu, b, 4)   << 16);
            if ((lane & 7) == 0) {
                int c = kb * 8 + half * 4 + (lane >> 3);
                g_wbits[c * NOUT + n] = m;
            }
        }
    }
}

// ---------------- main GEMM: out = (x_fp16 @ Wb^T) * round(max(s,1)) ----------------
// f16-accumulate HMMA; explicit fragment double-buffer (prefetch h+1 LDSM under h MMAs);
// promote (k8 identity MMA) runs in the h=0 LDSM shadow. 3 CTAs/SM.
__global__ void __launch_bounds__(THREADS, 3)
SBNLinear_39754217292616_kernel(const float* __restrict__ s, float* __restrict__ out) {
    extern __shared__ char smem[];
    const uint32_t sb = smem_u32(smem);
    const int tid = threadIdx.x;
    const int lane = tid & 31;
    const int wid = tid >> 5;                // 0..3
    const int m0 = blockIdx.x * BM;
    const int n0 = blockIdx.y * BN;
    const int m_off = (wid >> 1) * 32;       // 2 warps in M, 32 rows each
    const int n_off = (wid & 1) * 64;        // 2 warps in N, 64 cols each

    // identity fragment (fp16 I8) for the k8 promotion MMA
    const int q = lane >> 2, p = lane & 3;
    const uint32_t idf = ((2 * p == q) ? 0x3C00u : 0u) | ((2 * p + 1 == q) ? 0x3C000000u : 0u);

    float acc32[2][8][4];
    uint32_t acc16[2][8][2];
    #pragma unroll
    for (int mi = 0; mi < 2; ++mi)
        #pragma unroll
        for (int nj = 0; nj < 8; ++nj) {
            acc16[mi][nj][0] = 0u; acc16[mi][nj][1] = 0u;
            #pragma unroll
            for (int e = 0; e < 4; ++e) acc32[mi][nj][e] = 0.0f;
        }

    // double-buffered fragments
    uint32_t fa[2][2][4];     // [buf][mi][reg]
    uint32_t fb[2][4][4];     // [buf][g][reg]

    auto issueA = [&](int c, int buf) {
        #pragma unroll
        for (int i = 0; i < 4; ++i) {
            int qx = tid + i * THREADS;          // 0..511
            int row = qx >> 3;
            int ch = qx & 7;
            uint32_t dst = sb + buf * STAGE_BYTES + row * A_ROW_B + ch * 16;
            const __half* src = &g_xh[(size_t)(m0 + row) * KDIM + c * BK + ch * 8];
            asm volatile("cp.async.cg.shared.global [%0], [%1], 16;\n" :: "r"(dst), "l"(src) : "memory");
        }
    };
    auto stsB = [&](uint2 bits, int buf) {
        uint32_t dst = sb + buf * STAGE_BYTES + A_BYTES + tid * B_ROW_B;
        #pragma unroll
        for (int j = 0; j < 8; ++j) {
            unsigned b8 = ((j < 4 ? bits.x : bits.y) >> ((j & 3) * 8)) & 0xFFu;
            uint32_t u0, u1, u2, u3;
            u0 = (b8 & 1u   ? 0x3C00u : 0u) | (b8 & 2u   ? 0x3C000000u : 0u);
            u1 = (b8 & 4u   ? 0x3C00u : 0u) | (b8 & 8u   ? 0x3C000000u : 0u);
            u2 = (b8 & 16u  ? 0x3C00u : 0u) | (b8 & 32u  ? 0x3C000000u : 0u);
            u3 = (b8 & 64u  ? 0x3C00u : 0u) | (b8 & 128u ? 0x3C000000u : 0u);
            asm volatile("st.shared.v4.b32 [%0], {%1,%2,%3,%4};\n"
                         :: "r"(dst + j * 16), "r"(u0), "r"(u1), "r"(u2), "r"(u3) : "memory");
        }
    };
    auto loadBits = [&](int c) -> uint2 {
        uint2 r;
        r.x = g_wbits[(2 * c) * NOUT + n0 + tid];
        r.y = g_wbits[(2 * c + 1) * NOUT + n0 + tid];
        return r;
    };
    auto ldFrags = [&](uint32_t ab, uint32_t bb, int h, int buf) {
        #pragma unroll
        for (int mi = 0; mi < 2; ++mi) {
            uint32_t addr = ab + (uint32_t)(m_off + 16 * mi + (lane & 15)) * A_ROW_B
                               + (uint32_t)(2 * h + (lane >> 4)) * 16;
            asm volatile("ldmatrix.sync.aligned.m8n8.x4.shared.b16 {%0,%1,%2,%3}, [%4];\n"
                         : "=r"(fa[buf][mi][0]), "=r"(fa[buf][mi][1]),
                           "=r"(fa[buf][mi][2]), "=r"(fa[buf][mi][3])
                         : "r"(addr));
        }
        #pragma unroll
        for (int g = 0; g < 4; ++g) {
            int row = n_off + 16 * g + ((lane >> 4) << 3) + (lane & 7);
            uint32_t addr = bb + (uint32_t)row * B_ROW_B
                               + (uint32_t)(2 * h + ((lane >> 3) & 1)) * 16;
            asm volatile("ldmatrix.sync.aligned.m8n8.x4.shared.b16 {%0,%1,%2,%3}, [%4];\n"
                         : "=r"(fb[buf][g][0]), "=r"(fb[buf][g][1]),
                           "=r"(fb[buf][g][2]), "=r"(fb[buf][g][3])
                         : "r"(addr));
        }
    };
    auto mmaStep = [&](int buf) {
        #pragma unroll
        for (int g = 0; g < 4; ++g)
            #pragma unroll
            for (int mi = 0; mi < 2; ++mi) {
                asm volatile(
                    "mma.sync.aligned.m16n8k16.row.col.f16.f16.f16.f16 "
                    "{%0,%1}, {%2,%3,%4,%5}, {%6,%7}, {%0,%1};\n"
                    : "+r"(acc16[mi][2 * g][0]), "+r"(acc16[mi][2 * g][1])
                    : "r"(fa[buf][mi][0]), "r"(fa[buf][mi][1]),
                      "r"(fa[buf][mi][2]), "r"(fa[buf][mi][3]),
                      "r"(fb[buf][g][0]), "r"(fb[buf][g][1]));
                asm volatile(
                    "mma.sync.aligned.m16n8k16.row.col.f16.f16.f16.f16 "
                    "{%0,%1}, {%2,%3,%4,%5}, {%6,%7}, {%0,%1};\n"
                    : "+r"(acc16[mi][2 * g + 1][0]), "+r"(acc16[mi][2 * g + 1][1])
                    : "r"(fa[buf][mi][0]), "r"(fa[buf][mi][1]),
                      "r"(fa[buf][mi][2]), "r"(fa[buf][mi][3]),
                      "r"(fb[buf][g][2]), "r"(fb[buf][g][3]));
            }
    };
    // promote f16 segment accumulators into fp32 on the tensor pipe (k8 identity MMA)
    auto promote = [&]() {
        #pragma unroll
        for (int mi = 0; mi < 2; ++mi)
            #pragma unroll
            for (int nj = 0; nj < 8; ++nj) {
                asm volatile(
                    "mma.sync.aligned.m16n8k8.row.col.f32.f16.f16.f32 "
                    "{%0,%1,%2,%3}, {%4,%5}, {%6}, {%0,%1,%2,%3};\n"
                    : "+f"(acc32[mi][nj][0]), "+f"(acc32[mi][nj][1]),
                      "+f"(acc32[mi][nj][2]), "+f"(acc32[mi][nj][3])
                    : "r"(acc16[mi][nj][0]), "r"(acc16[mi][nj][1]), "r"(idf));
                acc16[mi][nj][0] = 0u;
                acc16[mi][nj][1] = 0u;
            }
    };

    // prologue: fill buffer 0 with chunk 0
    issueA(0, 0);
    asm volatile("cp.async.commit_group;\n" ::: "memory");
    stsB(loadBits(0), 0);
    uint2 bits_next = loadBits(1);

    for (int c = 0; c < NUM_K; ++c) {
        const int cur = c & 1;
        asm volatile("cp.async.wait_group 0;\n" ::: "memory");   // A(c) resident
        __syncthreads();                                         // stsB(c) visible, other buf free

        const uint32_t ab = sb + cur * STAGE_BYTES;
        const uint32_t bb = ab + A_BYTES;

        // start h=0 fragment loads immediately; fill their latency with
        // next-stage staging work and the (tensor-only) promote of chunk c-1.
        ldFrags(ab, bb, 0, 0);

        const int cn = c + 1;
        if (cn < NUM_K) {
            const int nxt = cn & 1;
            stsB(bits_next, nxt);
            issueA(cn, nxt);
            asm volatile("cp.async.commit_group;\n" ::: "memory");
            if (cn + 1 < NUM_K)
                bits_next = loadBits(cn + 1);
        }

        promote();   // chunk c-1's acc16 (zeros on c==0: adds 0, keeps code branch-free)

        #pragma unroll
        for (int h = 0; h < 4; ++h) {
            if (h < 3) ldFrags(ab, bb, h + 1, (h + 1) & 1);  // prefetch under MMAs
            mmaStep(h & 1);
        }
    }
    promote();       // final chunk's segment

    // epilogue: fuse s_eff = rint(max(s,1)) and store
    float sc[8][2];
    #pragma unroll
    for (int nj = 0; nj < 8; ++nj) {
        int col = n0 + n_off + 8 * nj + 2 * (lane & 3);
        sc[nj][0] = rintf(fmaxf(s[col], 1.0f));
        sc[nj][1] = rintf(fmaxf(s[col + 1], 1.0f));
    }
    #pragma unroll
    for (int mi = 0; mi < 2; ++mi) {
        int r0 = m0 + m_off + 16 * mi + (lane >> 2);
        #pragma unroll
        for (int nj = 0; nj < 8; ++nj) {
            int col = n0 + n_off + 8 * nj + 2 * (lane & 3);
            float2 v0 = make_float2(acc32[mi][nj][0] * sc[nj][0], acc32[mi][nj][1] * sc[nj][1]);
            float2 v1 = make_float2(acc32[mi][nj][2] * sc[nj][0], acc32[mi][nj][3] * sc[nj][1]);
            *(float2*)(out + (size_t)r0 * NOUT + col) = v0;
            *(float2*)(out + (size_t)(r0 + 8) * NOUT + col) = v1;
        }
    }
}

extern "C" void kernel_launch(void* const* d_in, const int* in_sizes, int n_in,
                              void* d_out, int out_size) {
    (void)in_sizes; (void)n_in; (void)out_size;
    const float* x = (const float*)d_in[0];
    const float* w = (const float*)d_in[1];
    const float* s = (const float*)d_in[2];
    float* out = (float*)d_out;

    prepass_kernel<<<CONV_BLOCKS + PACK_BLOCKS, 256>>>(x, w);

    cudaFuncSetAttribute(SBNLinear_39754217292616_kernel,
                         cudaFuncAttributeMaxDynamicSharedMemorySize, SMEM_TOTAL);
    dim3 grid(MTOK / BM, NOUT / BN);   // 16 x 32 = 512 CTAs, 3 resident/SM
    SBNLinear_39754217292616_kernel<<<grid, THREADS, SMEM_TOTAL>>>(s, out);
}

// round 10
// speedup vs baseline: 1.0348x; 1.0143x over previous
#include <cuda_runtime.h>
#include <cuda_fp16.h>
#include <cstdint>

#define DINL __device__ __forceinline__

namespace {
constexpr int KDIM = 4096;   // in_features
constexpr int NOUT = 4096;   // out_features
constexpr int MTOK = 1024;   // tokens

constexpr int BM = 128;      // CTA tile M
constexpr int BN = 128;      // CTA tile N
constexpr int BK = 64;       // K per stage (chunk)
constexpr int NUM_K = KDIM / BK;   // 64
constexpr int STAGES = 3;
constexpr int THREADS = 128; // 4 warps: 2 in M x 2 in N (64x64 per warp)

constexpr int A_ROW_B = 144;                // 64 halves (128B) + 16B pad -> conflict-free ldmatrix
constexpr int B_ROW_B = 144;
constexpr int A_BYTES = BM * A_ROW_B;       // 18432
constexpr int B_BYTES = BN * B_ROW_B;       // 18432
constexpr int STAGE_BYTES = A_BYTES + B_BYTES;   // 36864
constexpr int SMEM_TOTAL = STAGES * STAGE_BYTES; // 110592 -> 2 CTAs/SM

constexpr int CONV_BLOCKS = (MTOK * KDIM / 16) / 256;           // 1024  (4 float4/thread)
constexpr int PACK_BLOCKS = (NOUT * (KDIM / 256)) / 8;          // 8192  (1 warp = 256 K-values)
}  // namespace

// Scratch (static device globals: allowed; no runtime allocation).
__device__ __align__(16) __half g_xh[(size_t)MTOK * KDIM];                  // 8 MB fp16 x
// binarized W as fp16 {0,1}, chunk-major: g_wh[(c*NOUT + n)*BK + kk]
__device__ __align__(16) __half g_wh[(size_t)(KDIM / BK) * NOUT * BK];      // 33.5 MB

DINL uint32_t smem_u32(const void* p) {
    uint32_t a;
    asm("{ .reg .u64 t; cvta.to.shared.u64 t, %1; cvt.u32.u64 %0, t; }" : "=r"(a) : "l"(p));
    return a;
}

// ---------------- fused prepass: x->fp16  +  binarize W -> fp16 {0,1} chunk-major ----------------
__global__ void __launch_bounds__(256) prepass_kernel(const float* __restrict__ x,
                                                      const float* __restrict__ w) {
    if (blockIdx.x < CONV_BLOCKS) {
        // 4 independent float4 per thread (MLP=4)
        int base = blockIdx.x * 256 + threadIdx.x;
        float4 v[4];
        #pragma unroll
        for (int j = 0; j < 4; ++j)
            v[j] = __ldcs((const float4*)x + base + j * (CONV_BLOCKS * 256));
        #pragma unroll
        for (int j = 0; j < 4; ++j) {
            __half2 h0 = __floats2half2_rn(v[j].x, v[j].y);
            __half2 h1 = __floats2half2_rn(v[j].z, v[j].w);
            uint2 u;
            u.x = *(const uint32_t*)&h0;
            u.y = *(const uint32_t*)&h1;
            *(uint2*)(&g_xh[(size_t)(base + j * (CONV_BLOCKS * 256)) * 4]) = u;
        }
    } else {
        // one warp binarizes 256 K-values (2x float4/lane) of one W row -> fp16 {0,1}
        int pb = blockIdx.x - CONV_BLOCKS;
        int lane = threadIdx.x & 31;
        int wg = pb * 8 + (threadIdx.x >> 5);   // global warp id
        int n = wg & (NOUT - 1);
        int kb = wg >> 12;                      // 256-wide K block, 0..15
        const float4* src = (const float4*)(w + (size_t)n * KDIM + kb * 256);
        #pragma unroll
        for (int half = 0; half < 2; ++half) {
            const float4 v = __ldcs(src + half * 32 + lane);
            // 4 halves {0,1}
            uint2 u;
            u.x = (v.x > 0.f ? 0x3C00u : 0u) | (v.y > 0.f ? 0x3C000000u : 0u);
            u.y = (v.z > 0.f ? 0x3C00u : 0u) | (v.w > 0.f ? 0x3C000000u : 0u);
            int kloc = half * 128 + lane * 4;          // 0..255 within the 256-K block
            int c = kb * 4 + (kloc >> 6);              // BK=64 chunk index
            int kk = kloc & 63;
            *(uint2*)(&g_wh[((size_t)c * NOUT + n) * BK + kk]) = u;
        }
    }
}

// ---------------- main GEMM: out = (x_fp16 @ Wb^T) * round(max(s,1)) ----------------
// Pure cp.async staging for BOTH operands (B pre-binarized to fp16 in prepass).
// f16-accumulate HMMA; fp32 promotion every chunk (64 K) via k8 identity-B MMA.
__global__ void __launch_bounds__(THREADS, 2)
SBNLinear_39754217292616_kernel(const float* __restrict__ s, float* __restrict__ out) {
    extern __shared__ char smem[];
    const uint32_t sb = smem_u32(smem);
    const int tid = threadIdx.x;
    const int lane = tid & 31;
    const int wid = tid >> 5;                // 0..3
    const int m0 = blockIdx.x * BM;
    const int n0 = blockIdx.y * BN;
    const int m_off = (wid >> 1) * 64;       // 2 warps in M
    const int n_off = (wid & 1) * 64;        // 2 warps in N

    // identity fragment (fp16 I8) for the k8 promotion MMA
    const int q = lane >> 2, p = lane & 3;
    const uint32_t idf = ((2 * p == q) ? 0x3C00u : 0u) | ((2 * p + 1 == q) ? 0x3C000000u : 0u);

    float acc32[4][8][4];
    uint32_t acc16[4][8][2];
    #pragma unroll
    for (int mi = 0; mi < 4; ++mi)
        #pragma unroll
        for (int nj = 0; nj < 8; ++nj) {
            acc16[mi][nj][0] = 0u; acc16[mi][nj][1] = 0u;
            #pragma unroll
            for (int e = 0; e < 4; ++e) acc32[mi][nj][e] = 0.0f;
        }

    // A tile: 128 rows x 128B = 1024 x 16B, 8 cp.async per thread
    auto issueA = [&](int c, int buf) {
        #pragma unroll
        for (int i = 0; i < 8; ++i) {
            int qx = tid + i * THREADS;          // 0..1023
            int row = qx >> 3;
            int ch = qx & 7;
            uint32_t dst = sb + buf * STAGE_BYTES + row * A_ROW_B + ch * 16;
            const __half* src = &g_xh[(size_t)(m0 + row) * KDIM + c * BK + ch * 8];
            asm volatile("cp.async.cg.shared.global [%0], [%1], 16;\n" :: "r"(dst), "l"(src) : "memory");
        }
    };
    // B tile: 128 rows x 128B (chunk-major in gmem -> contiguous per row)
    auto issueB = [&](int c, int buf) {
        #pragma unroll
        for (int i = 0; i < 8; ++i) {
            int qx = tid + i * THREADS;          // 0..1023
            int row = qx >> 3;
            int ch = qx & 7;
            uint32_t dst = sb + buf * STAGE_BYTES + A_BYTES + row * B_ROW_B + ch * 16;
            const __half* src = &g_wh[((size_t)c * NOUT + n0 + row) * BK + ch * 8];
            asm volatile("cp.async.cg.shared.global [%0], [%1], 16;\n" :: "r"(dst), "l"(src) : "memory");
        }
    };

    // prologue: stages 0..1
    #pragma unroll
    for (int c = 0; c < STAGES - 1; ++c) {
        issueA(c, c);
        issueB(c, c);
        asm volatile("cp.async.commit_group;\n" ::: "memory");
    }

    for (int c = 0; c < NUM_K; ++c) {
        const int buf = c % 3;
        if (c < NUM_K - 2) asm volatile("cp.async.wait_group 1;\n" ::: "memory");
        else               asm volatile("cp.async.wait_group 0;\n" ::: "memory");
        __syncthreads();

        const int cn = c + 2;
        if (cn < NUM_K) {
            const int nbuf = cn % 3;
            issueA(cn, nbuf);
            issueB(cn, nbuf);
            asm volatile("cp.async.commit_group;\n" ::: "memory");
        }

        const uint32_t ab = sb + buf * STAGE_BYTES;
        const uint32_t bb = ab + A_BYTES;
        #pragma unroll
        for (int h = 0; h < 4; ++h) {
            uint32_t a[4][4];
            #pragma unroll
            for (int mi = 0; mi < 4; ++mi) {
                uint32_t addr = ab + (uint32_t)(m_off + 16 * mi + (lane & 15)) * A_ROW_B
                                   + (uint32_t)(2 * h + (lane >> 4)) * 16;
                asm volatile("ldmatrix.sync.aligned.m8n8.x4.shared.b16 {%0,%1,%2,%3}, [%4];\n"
                             : "=r"(a[mi][0]), "=r"(a[mi][1]), "=r"(a[mi][2]), "=r"(a[mi][3])
                             : "r"(addr));
            }
            #pragma unroll
            for (int g = 0; g < 4; ++g) {
                int row = n_off + 16 * g + ((lane >> 4) << 3) + (lane & 7);
                uint32_t addr = bb + (uint32_t)row * B_ROW_B
                                   + (uint32_t)(2 * h + ((lane >> 3) & 1)) * 16;
                uint32_t r0, r1, r2, r3;
                asm volatile("ldmatrix.sync.aligned.m8n8.x4.shared.b16 {%0,%1,%2,%3}, [%4];\n"
                             : "=r"(r0), "=r"(r1), "=r"(r2), "=r"(r3) : "r"(addr));
                #pragma unroll
                for (int mi = 0; mi < 4; ++mi) {
                    asm volatile(
                        "mma.sync.aligned.m16n8k16.row.col.f16.f16.f16.f16 "
                        "{%0,%1}, {%2,%3,%4,%5}, {%6,%7}, {%0,%1};\n"
                        : "+r"(acc16[mi][2 * g][0]), "+r"(acc16[mi][2 * g][1])
                        : "r"(a[mi][0]), "r"(a[mi][1]), "r"(a[mi][2]), "r"(a[mi][3]),
                          "r"(r0), "r"(r1));
                    asm volatile(
                        "mma.sync.aligned.m16n8k16.row.col.f16.f16.f16.f16 "
                        "{%0,%1}, {%2,%3,%4,%5}, {%6,%7}, {%0,%1};\n"
                        : "+r"(acc16[mi][2 * g + 1][0]), "+r"(acc16[mi][2 * g + 1][1])
                        : "r"(a[mi][0]), "r"(a[mi][1]), "r"(a[mi][2]), "r"(a[mi][3]),
                          "r"(r2), "r"(r3));
                }
            }
        }

        // promote f16 segment accumulators (64 K-steps) into fp32 on the tensor pipe:
        // D-fragment {c01,c23} IS the k8 A-fragment -> acc32 += acc16 x I8
        #pragma unroll
        for (int mi = 0; mi < 4; ++mi)
            #pragma unroll
            for (int nj = 0; nj < 8; ++nj) {
                asm volatile(
                    "mma.sync.aligned.m16n8k8.row.col.f32.f16.f16.f32 "
                    "{%0,%1,%2,%3}, {%4,%5}, {%6}, {%0,%1,%2,%3};\n"
                    : "+f"(acc32[mi][nj][0]), "+f"(acc32[mi][nj][1]),
                      "+f"(acc32[mi][nj][2]), "+f"(acc32[mi][nj][3])
                    : "r"(acc16[mi][nj][0]), "r"(acc16[mi][nj][1]), "r"(idf));
                acc16[mi][nj][0] = 0u;
                acc16[mi][nj][1] = 0u;
            }
    }

    // epilogue: fuse s_eff = rint(max(s,1)) and store
    float sc[8][2];
    #pragma unroll
    for (int nj = 0; nj < 8; ++nj) {
        int col = n0 + n_off + 8 * nj + 2 * (lane & 3);
        sc[nj][0] = rintf(fmaxf(s[col], 1.0f));
        sc[nj][1] = rintf(fmaxf(s[col + 1], 1.0f));
    }
    #pragma unroll
    for (int mi = 0; mi < 4; ++mi) {
        int r0 = m0 + m_off + 16 * mi + (lane >> 2);
        #pragma unroll
        for (int nj = 0; nj < 8; ++nj) {
            int col = n0 + n_off + 8 * nj + 2 * (lane & 3);
            float2 v0 = make_float2(acc32[mi][nj][0] * sc[nj][0], acc32[mi][nj][1] * sc[nj][1]);
            float2 v1 = make_float2(acc32[mi][nj][2] * sc[nj][0], acc32[mi][nj][3] * sc[nj][1]);
            *(float2*)(out + (size_t)r0 * NOUT + col) = v0;
            *(float2*)(out + (size_t)(r0 + 8) * NOUT + col) = v1;
        }
    }
}

extern "C" void kernel_launch(void* const* d_in, const int* in_sizes, int n_in,
                              void* d_out, int out_size) {
    (void)in_sizes; (void)n_in; (void)out_size;
    const float* x = (const float*)d_in[0];
    const float* w = (const float*)d_in[1];
    const float* s = (const float*)d_in[2];
    float* out = (float*)d_out;

    prepass_kernel<<<CONV_BLOCKS + PACK_BLOCKS, 256>>>(x, w);

    cudaFuncSetAttribute(SBNLinear_39754217292616_kernel,
                         cudaFuncAttributeMaxDynamicSharedMemorySize, SMEM_TOTAL);
    dim3 grid(MTOK / BM, NOUT / BN);   // 8 x 32 = 256 CTAs, 2 resident/SM
    SBNLinear_39754217292616_kernel<<<grid, THREADS, SMEM_TOTAL>>>(s, out);
}

// round 11
// speedup vs baseline: 1.0366x; 1.0017x over previous
#include <cuda_runtime.h>
#include <cuda_fp16.h>
#include <cstdint>

#define DINL __device__ __forceinline__

namespace {
constexpr int KDIM = 4096;   // in_features
constexpr int NOUT = 4096;   // out_features
constexpr int MTOK = 1024;   // tokens

constexpr int BM = 128;      // CTA tile M
constexpr int BN = 128;      // CTA tile N
constexpr int BK = 64;       // K per stage (chunk)
constexpr int NUM_K = KDIM / BK;   // 64
constexpr int STAGES = 3;
constexpr int THREADS = 128; // 4 warps: 2 in M x 2 in N (64x64 per warp)

constexpr int A_ROW_B = 144;                // 64 halves (128B) + 16B pad -> conflict-free ldmatrix
constexpr int B_ROW_B = 144;
constexpr int A_BYTES = BM * A_ROW_B;       // 18432
constexpr int B_BYTES = BN * B_ROW_B;       // 18432
constexpr int STAGE_BYTES = A_BYTES + B_BYTES;   // 36864
constexpr int SMEM_TOTAL = STAGES * STAGE_BYTES; // 110592 -> 2 CTAs/SM

constexpr int CONV_BLOCKS = (MTOK * KDIM / 16) / 256;           // 1024  (4 float4/thread)
constexpr int PACK_BLOCKS = (NOUT * (KDIM / 256)) / 8;          // 8192  (1 warp = 256 K-values)
}  // namespace

// Scratch (static device globals: allowed; no runtime allocation).
__device__ __align__(16) __half g_xh[(size_t)MTOK * KDIM];                  // 8 MB fp16 x
// binarized W as fp16 {0,1}, chunk-major: g_wh[(c*NOUT + n)*BK + kk]
__device__ __align__(16) __half g_wh[(size_t)(KDIM / BK) * NOUT * BK];      // 33.5 MB

DINL uint32_t smem_u32(const void* p) {
    uint32_t a;
    asm("{ .reg .u64 t; cvta.to.shared.u64 t, %1; cvt.u32.u64 %0, t; }" : "=r"(a) : "l"(p));
    return a;
}

// ---------------- fused prepass: x->fp16  +  binarize W -> fp16 {0,1} chunk-major ----------------
__global__ void __launch_bounds__(256) prepass_kernel(const float* __restrict__ x,
                                                      const float* __restrict__ w) {
    if (blockIdx.x < CONV_BLOCKS) {
        int base = blockIdx.x * 256 + threadIdx.x;
        float4 v[4];
        #pragma unroll
        for (int j = 0; j < 4; ++j)
            v[j] = __ldcs((const float4*)x + base + j * (CONV_BLOCKS * 256));
        #pragma unroll
        for (int j = 0; j < 4; ++j) {
            __half2 h0 = __floats2half2_rn(v[j].x, v[j].y);
            __half2 h1 = __floats2half2_rn(v[j].z, v[j].w);
            uint2 u;
            u.x = *(const uint32_t*)&h0;
            u.y = *(const uint32_t*)&h1;
            *(uint2*)(&g_xh[(size_t)(base + j * (CONV_BLOCKS * 256)) * 4]) = u;
        }
    } else {
        // one warp binarizes 256 K-values (2x float4/lane) of one W row -> fp16 {0,1}
        int pb = blockIdx.x - CONV_BLOCKS;
        int lane = threadIdx.x & 31;
        int wg = pb * 8 + (threadIdx.x >> 5);   // global warp id
        int n = wg & (NOUT - 1);
        int kb = wg >> 12;                      // 256-wide K block, 0..15
        const float4* src = (const float4*)(w + (size_t)n * KDIM + kb * 256);
        #pragma unroll
        for (int half = 0; half < 2; ++half) {
            const float4 v = __ldcs(src + half * 32 + lane);
            uint2 u;
            u.x = (v.x > 0.f ? 0x3C00u : 0u) | (v.y > 0.f ? 0x3C000000u : 0u);
            u.y = (v.z > 0.f ? 0x3C00u : 0u) | (v.w > 0.f ? 0x3C000000u : 0u);
            int kloc = half * 128 + lane * 4;          // 0..255 within the 256-K block
            int c = kb * 4 + (kloc >> 6);              // BK=64 chunk index
            int kk = kloc & 63;
            *(uint2*)(&g_wh[((size_t)c * NOUT + n) * BK + kk]) = u;
        }
    }
}

// ---------------- main GEMM: out = (x_fp16 @ Wb^T) * round(max(s,1)) ----------------
// f16-accumulate HMMA. Each chunk is processed in two nj-halves so only 32 acc16
// registers are live at a time (frees ~40 regs for ptxas software pipelining).
// Promotion (k8 identity MMA) per half; 64-K segments -> numerics unchanged.
__global__ void __launch_bounds__(THREADS, 2)
SBNLinear_39754217292616_kernel(const float* __restrict__ s, float* __restrict__ out) {
    extern __shared__ char smem[];
    const uint32_t sb = smem_u32(smem);
    const int tid = threadIdx.x;
    const int lane = tid & 31;
    const int wid = tid >> 5;                // 0..3
    const int m0 = blockIdx.x * BM;
    const int n0 = blockIdx.y * BN;
    const int m_off = (wid >> 1) * 64;       // 2 warps in M
    const int n_off = (wid & 1) * 64;        // 2 warps in N

    // identity fragment (fp16 I8) for the k8 promotion MMA
    const int q = lane >> 2, p = lane & 3;
    const uint32_t idf = ((2 * p == q) ? 0x3C00u : 0u) | ((2 * p + 1 == q) ? 0x3C000000u : 0u);

    float acc32[4][8][4];
    #pragma unroll
    for (int mi = 0; mi < 4; ++mi)
        #pragma unroll
        for (int nj = 0; nj < 8; ++nj)
            #pragma unroll
            for (int e = 0; e < 4; ++e) acc32[mi][nj][e] = 0.0f;

    uint32_t acc16[4][4][2];   // one nj-half at a time (32 regs)
    #pragma unroll
    for (int mi = 0; mi < 4; ++mi)
        #pragma unroll
        for (int nj = 0; nj < 4; ++nj) { acc16[mi][nj][0] = 0u; acc16[mi][nj][1] = 0u; }

    auto issueA = [&](int c, int buf) {
        #pragma unroll
        for (int i = 0; i < 8; ++i) {
            int qx = tid + i * THREADS;          // 0..1023
            int row = qx >> 3;
            int ch = qx & 7;
            uint32_t dst = sb + buf * STAGE_BYTES + row * A_ROW_B + ch * 16;
            const __half* src = &g_xh[(size_t)(m0 + row) * KDIM + c * BK + ch * 8];
            asm volatile("cp.async.cg.shared.global [%0], [%1], 16;\n" :: "r"(dst), "l"(src) : "memory");
        }
    };
    auto issueB = [&](int c, int buf) {
        #pragma unroll
        for (int i = 0; i < 8; ++i) {
            int qx = tid + i * THREADS;          // 0..1023
            int row = qx >> 3;
            int ch = qx & 7;
            uint32_t dst = sb + buf * STAGE_BYTES + A_BYTES + row * B_ROW_B + ch * 16;
            const __half* src = &g_wh[((size_t)c * NOUT + n0 + row) * BK + ch * 8];
            asm volatile("cp.async.cg.shared.global [%0], [%1], 16;\n" :: "r"(dst), "l"(src) : "memory");
        }
    };

    // prologue: stages 0..1
    #pragma unroll
    for (int c = 0; c < STAGES - 1; ++c) {
        issueA(c, c);
        issueB(c, c);
        asm volatile("cp.async.commit_group;\n" ::: "memory");
    }

    for (int c = 0; c < NUM_K; ++c) {
        const int buf = c % 3;
        if (c < NUM_K - 2) asm volatile("cp.async.wait_group 1;\n" ::: "memory");
        else               asm volatile("cp.async.wait_group 0;\n" ::: "memory");
        __syncthreads();

        const int cn = c + 2;
        if (cn < NUM_K) {
            const int nbuf = cn % 3;
            issueA(cn, nbuf);
            issueB(cn, nbuf);
            asm volatile("cp.async.commit_group;\n" ::: "memory");
        }

        const uint32_t ab = sb + buf * STAGE_BYTES;
        const uint32_t bb = ab + A_BYTES;

        #pragma unroll
        for (int half = 0; half < 2; ++half) {
            // accumulate this nj-half over all 4 h-steps
            #pragma unroll
            for (int h = 0; h < 4; ++h) {
                uint32_t a[4][4];
                #pragma unroll
                for (int mi = 0; mi < 4; ++mi) {
                    uint32_t addr = ab + (uint32_t)(m_off + 16 * mi + (lane & 15)) * A_ROW_B
                                       + (uint32_t)(2 * h + (lane >> 4)) * 16;
                    asm volatile("ldmatrix.sync.aligned.m8n8.x4.shared.b16 {%0,%1,%2,%3}, [%4];\n"
                                 : "=r"(a[mi][0]), "=r"(a[mi][1]), "=r"(a[mi][2]), "=r"(a[mi][3])
                                 : "r"(addr));
                }
                #pragma unroll
                for (int gl = 0; gl < 2; ++gl) {
                    int g = half * 2 + gl;
                    int row = n_off + 16 * g + ((lane >> 4) << 3) + (lane & 7);
                    uint32_t addr = bb + (uint32_t)row * B_ROW_B
                                       + (uint32_t)(2 * h + ((lane >> 3) & 1)) * 16;
                    uint32_t r0, r1, r2, r3;
                    asm volatile("ldmatrix.sync.aligned.m8n8.x4.shared.b16 {%0,%1,%2,%3}, [%4];\n"
                                 : "=r"(r0), "=r"(r1), "=r"(r2), "=r"(r3) : "r"(addr));
                    #pragma unroll
                    for (int mi = 0; mi < 4; ++mi) {
                        asm volatile(
                            "mma.sync.aligned.m16n8k16.row.col.f16.f16.f16.f16 "
                            "{%0,%1}, {%2,%3,%4,%5}, {%6,%7}, {%0,%1};\n"
                            : "+r"(acc16[mi][2 * gl][0]), "+r"(acc16[mi][2 * gl][1])
                            : "r"(a[mi][0]), "r"(a[mi][1]), "r"(a[mi][2]), "r"(a[mi][3]),
                              "r"(r0), "r"(r1));
                        asm volatile(
                            "mma.sync.aligned.m16n8k16.row.col.f16.f16.f16.f16 "
                            "{%0,%1}, {%2,%3,%4,%5}, {%6,%7}, {%0,%1};\n"
                            : "+r"(acc16[mi][2 * gl + 1][0]), "+r"(acc16[mi][2 * gl + 1][1])
                            : "r"(a[mi][0]), "r"(a[mi][1]), "r"(a[mi][2]), "r"(a[mi][3]),
                              "r"(r2), "r"(r3));
                    }
                }
            }
            // promote this half's 64-K segment into fp32 (tensor pipe, k8 identity)
            #pragma unroll
            for (int mi = 0; mi < 4; ++mi)
                #pragma unroll
                for (int njl = 0; njl < 4; ++njl) {
                    int nj = half * 4 + njl;
                    asm volatile(
                        "mma.sync.aligned.m16n8k8.row.col.f32.f16.f16.f32 "
                        "{%0,%1,%2,%3}, {%4,%5}, {%6}, {%0,%1,%2,%3};\n"
                        : "+f"(acc32[mi][nj][0]), "+f"(acc32[mi][nj][1]),
                          "+f"(acc32[mi][nj][2]), "+f"(acc32[mi][nj][3])
                        : "r"(acc16[mi][njl][0]), "r"(acc16[mi][njl][1]), "r"(idf));
                    acc16[mi][njl][0] = 0u;
                    acc16[mi][njl][1] = 0u;
                }
        }
    }

    // epilogue: fuse s_eff = rint(max(s,1)) and store
    float sc[8][2];
    #pragma unroll
    for (int nj = 0; nj < 8; ++nj) {
        int col = n0 + n_off + 8 * nj + 2 * (lane & 3);
        sc[nj][0] = rintf(fmaxf(s[col], 1.0f));
        sc[nj][1] = rintf(fmaxf(s[col + 1], 1.0f));
    }
    #pragma unroll
    for (int mi = 0; mi < 4; ++mi) {
        int r0 = m0 + m_off + 16 * mi + (lane >> 2);
        #pragma unroll
        for (int nj = 0; nj < 8; ++nj) {
            int col = n0 + n_off + 8 * nj + 2 * (lane & 3);
            float2 v0 = make_float2(acc32[mi][nj][0] * sc[nj][0], acc32[mi][nj][1] * sc[nj][1]);
            float2 v1 = make_float2(acc32[mi][nj][2] * sc[nj][0], acc32[mi][nj][3] * sc[nj][1]);
            *(float2*)(out + (size_t)r0 * NOUT + col) = v0;
            *(float2*)(out + (size_t)(r0 + 8) * NOUT + col) = v1;
        }
    }
}

extern "C" void kernel_launch(void* const* d_in, const int* in_sizes, int n_in,
                              void* d_out, int out_size) {
    (void)in_sizes; (void)n_in; (void)out_size;
    const float* x = (const float*)d_in[0];
    const float* w = (const float*)d_in[1];
    const float* s = (const float*)d_in[2];
    float* out = (float*)d_out;

    prepass_kernel<<<CONV_BLOCKS + PACK_BLOCKS, 256>>>(x, w);

    cudaFuncSetAttribute(SBNLinear_39754217292616_kernel,
                         cudaFuncAttributeMaxDynamicSharedMemorySize, SMEM_TOTAL);
    dim3 grid(MTOK / BM, NOUT / BN);   // 8 x 32 = 256 CTAs, 2 resident/SM
    SBNLinear_39754217292616_kernel<<<grid, THREADS, SMEM_TOTAL>>>(s, out);
}